// round 6
// baseline (speedup 1.0000x reference)
#include <cuda_runtime.h>
#include <cuda_bf16.h>

// CBOW hierarchical-softmax loss.
// Inputs (metadata order):
//   d_in[0] context_idxs  int32 [B, C]   B=65536, C=10
//   d_in[1] path_nodes    int32 [B, D]   D=18
//   d_in[2] codes         int32 [B, D]
//   d_in[3] in_embed      f32   [V, E]   V=100000, E=128
//   d_in[4] node_embed    f32   [N, E]   N=99999
// Output: loss f32 [B]
//
// R6: 256-bit gathers. Each lane loads 8 floats (32B); a half-warp covers a
//     512B row, so ONE wide load fetches TWO rows (half 0 -> row 2j,
//     half 1 -> row 2j+1). 28 row-LDGs/warp -> 14. L2::evict_last (legal on
//     256-bit loads) retains the ~102MB tables in L2 across graph replays.
//     4-step half-warp dot reduction, waves double-buffered for MLP,
//     launch_bounds(256,2) so all loads stay register-resident.

#define B_ 65536
#define C_ 10
#define D_ 18
#define E_ 128
#define EPS_ 1e-9f

typedef unsigned long long u64;

__device__ __forceinline__ u64 f32x2_add(u64 a, u64 b) {
    u64 r; asm("add.rn.f32x2 %0, %1, %2;" : "=l"(r) : "l"(a), "l"(b)); return r;
}
__device__ __forceinline__ u64 f32x2_mul(u64 a, u64 b) {
    u64 r; asm("mul.rn.f32x2 %0, %1, %2;" : "=l"(r) : "l"(a), "l"(b)); return r;
}
__device__ __forceinline__ u64 f32x2_fma(u64 a, u64 b, u64 c) {
    u64 r; asm("fma.rn.f32x2 %0, %1, %2, %3;" : "=l"(r) : "l"(a), "l"(b), "l"(c)); return r;
}
__device__ __forceinline__ u64 pack2(float lo, float hi) {
    u64 r; asm("mov.b64 %0, {%1, %2};" : "=l"(r) : "f"(lo), "f"(hi)); return r;
}
__device__ __forceinline__ float2 unpack2(u64 v) {
    float2 f; asm("mov.b64 {%0, %1}, %2;" : "=f"(f.x), "=f"(f.y) : "l"(v)); return f;
}
__device__ __forceinline__ u64 shfl_xor_u64(u64 v, int o) {
    uint2 t; asm("mov.b64 {%0, %1}, %2;" : "=r"(t.x), "=r"(t.y) : "l"(v));
    t.x = __shfl_xor_sync(0xFFFFFFFFu, t.x, o);
    t.y = __shfl_xor_sync(0xFFFFFFFFu, t.y, o);
    u64 r; asm("mov.b64 %0, {%1, %2};" : "=l"(r) : "r"(t.x), "r"(t.y));
    return r;
}
// 32B (8-float) gather, non-coherent, L2 keep-resident.
__device__ __forceinline__ void ldrow256(const float* p, u64& a, u64& b, u64& c, u64& d) {
    asm("ld.global.nc.L2::evict_last.v4.u64 {%0, %1, %2, %3}, [%4];"
        : "=l"(a), "=l"(b), "=l"(c), "=l"(d) : "l"(p));
}

__global__ void __launch_bounds__(256, 2) cbow_hs_kernel(
    const int* __restrict__ ctx,
    const int* __restrict__ path,
    const int* __restrict__ codes,
    const float* __restrict__ in_emb,
    const float* __restrict__ node_emb,
    float* __restrict__ out)
{
    const int warp = (blockIdx.x * blockDim.x + threadIdx.x) >> 5;
    const int lane = threadIdx.x & 31;
    if (warp >= B_) return;

    const int half = lane >> 4;          // 0: even row of pair, 1: odd row
    const int col8 = (lane & 15) * 8;    // this lane's 8-float column slice

    // ---- index/code loads (small, independent, issued first) ----
    const int2* __restrict__ ctx2 = reinterpret_cast<const int2*>(ctx + warp * C_);
    const int2* __restrict__ pn2  = reinterpret_cast<const int2*>(path + warp * D_);
    int csel[C_ / 2];   // per-lane: index of the row THIS half loads, per pair
#pragma unroll
    for (int j = 0; j < C_ / 2; j++) {
        int2 c = __ldg(&ctx2[j]);
        csel[j] = half ? c.y : c.x;
    }
    int psel_idx[D_ / 2];
#pragma unroll
    for (int j = 0; j < D_ / 2; j++) {
        int2 p = __ldg(&pn2[j]);
        psel_idx[j] = half ? p.y : p.x;
    }
    int code_l = 0;
    if (lane < D_) code_l = __ldg(&codes[warp * D_ + lane]);

    // ---- ctx wave: 5 wide loads fetch all 10 context rows ----
    u64 ce[C_ / 2][4];
#pragma unroll
    for (int j = 0; j < C_ / 2; j++)
        ldrow256(in_emb + (size_t)csel[j] * E_ + col8,
                 ce[j][0], ce[j][1], ce[j][2], ce[j][3]);

    // ---- node wave 0 in flight before ctx is consumed ----
    u64 w0[3][4], w1[3][4];
#pragma unroll
    for (int j = 0; j < 3; j++)
        ldrow256(node_emb + (size_t)psel_idx[j] * E_ + col8,
                 w0[j][0], w0[j][1], w0[j][2], w0[j][3]);

    // ---- mean: sum within half, one cross-half add, scale ----
    u64 v0 = ce[0][0], v1 = ce[0][1], v2 = ce[0][2], v3 = ce[0][3];
#pragma unroll
    for (int j = 1; j < C_ / 2; j++) {
        v0 = f32x2_add(v0, ce[j][0]);
        v1 = f32x2_add(v1, ce[j][1]);
        v2 = f32x2_add(v2, ce[j][2]);
        v3 = f32x2_add(v3, ce[j][3]);
    }
    v0 = f32x2_add(v0, shfl_xor_u64(v0, 16));
    v1 = f32x2_add(v1, shfl_xor_u64(v1, 16));
    v2 = f32x2_add(v2, shfl_xor_u64(v2, 16));
    v3 = f32x2_add(v3, shfl_xor_u64(v3, 16));
    const u64 inv = pack2(1.0f / (float)C_, 1.0f / (float)C_);
    v0 = f32x2_mul(v0, inv); v1 = f32x2_mul(v1, inv);
    v2 = f32x2_mul(v2, inv); v3 = f32x2_mul(v3, inv);

    // ---- node waves (double-buffered): partial dot per lane ----
    float part[D_ / 2];    // part[j] = partial of node 2j+half
#pragma unroll
    for (int j = 0; j < 3; j++)   // wave 1 in flight
        ldrow256(node_emb + (size_t)psel_idx[3 + j] * E_ + col8,
                 w1[j][0], w1[j][1], w1[j][2], w1[j][3]);
#pragma unroll
    for (int j = 0; j < 3; j++) { // consume wave 0
        u64 m = f32x2_mul(w0[j][0], v0);
        m = f32x2_fma(w0[j][1], v1, m);
        m = f32x2_fma(w0[j][2], v2, m);
        m = f32x2_fma(w0[j][3], v3, m);
        float2 f = unpack2(m);
        part[j] = f.x + f.y;
    }
#pragma unroll
    for (int j = 0; j < 3; j++)   // wave 2 in flight (reuse w0 slots)
        ldrow256(node_emb + (size_t)psel_idx[6 + j] * E_ + col8,
                 w0[j][0], w0[j][1], w0[j][2], w0[j][3]);
#pragma unroll
    for (int j = 0; j < 3; j++) { // consume wave 1
        u64 m = f32x2_mul(w1[j][0], v0);
        m = f32x2_fma(w1[j][1], v1, m);
        m = f32x2_fma(w1[j][2], v2, m);
        m = f32x2_fma(w1[j][3], v3, m);
        float2 f = unpack2(m);
        part[3 + j] = f.x + f.y;
    }
#pragma unroll
    for (int j = 0; j < 3; j++) { // consume wave 2
        u64 m = f32x2_mul(w0[j][0], v0);
        m = f32x2_fma(w0[j][1], v1, m);
        m = f32x2_fma(w0[j][2], v2, m);
        m = f32x2_fma(w0[j][3], v3, m);
        float2 f = unpack2(m);
        part[6 + j] = f.x + f.y;
    }

    // ---- 4-step butterfly within half-warp: s_{2j+half} in every lane ----
#pragma unroll
    for (int o = 8; o > 0; o >>= 1) {
#pragma unroll
        for (int j = 0; j < D_ / 2; j++)
            part[j] += __shfl_xor_sync(0xFFFFFFFFu, part[j], o);
    }

    // ---- route s_d to lane d ----
    // lane l prepares part[l & 15]; lane d reads from lane 16*(d&1) + (d>>1).
    const int sel = lane & 15;
    float prep = part[0];
#pragma unroll
    for (int j = 1; j < D_ / 2; j++)
        prep = (sel == j) ? part[j] : prep;
    float s = __shfl_sync(0xFFFFFFFFu, prep, ((lane & 1) << 4) | (lane >> 1));

    // ---- epilogue once per warp (3 MUFU total) ----
    float x = code_l ? s : -s;   // p = sigmoid(x) if code==1 else sigmoid(-x)
    float sig = __fdividef(1.0f, 1.0f + __expf(-x));
    float term = __logf(sig + EPS_);
    term = (lane < D_) ? term : 0.f;

#pragma unroll
    for (int o = 16; o > 0; o >>= 1)
        term += __shfl_xor_sync(0xFFFFFFFFu, term, o);

    if (lane == 0)
        out[warp] = -term;
}

extern "C" void kernel_launch(void* const* d_in, const int* in_sizes, int n_in,
                              void* d_out, int out_size)
{
    const int*   ctx      = (const int*)d_in[0];
    const int*   path     = (const int*)d_in[1];
    const int*   codes    = (const int*)d_in[2];
    const float* in_emb   = (const float*)d_in[3];
    const float* node_emb = (const float*)d_in[4];
    float*       out      = (float*)d_out;

    const int threads = 256;               // 8 warps/block
    const int total   = B_ * 32;
    const int blocks  = (total + threads - 1) / threads;
    cbow_hs_kernel<<<blocks, threads>>>(ctx, path, codes, in_emb, node_emb, out);
}